// round 14
// baseline (speedup 1.0000x reference)
#include <cuda_runtime.h>

#define IMG 4096
#define TILE_X 56          // owned pixels per tile in x
#define TILE_Y 120         // owned pixels per tile in y
#define SSTR 72            // halo-row stride in floats
#define NITER 5
#define NTX ((IMG + TILE_X - 1) / TILE_X)    // 74
#define NTY ((IMG + TILE_Y - 1) / TILE_Y)    // 35
#define NBLK (NTX * NTY)                     // 2590

// [0] = gt_sum, [1] = weighted fn sum  (reset by the last block each run)
__device__ float g_sums[2];
__device__ unsigned int g_count;

__device__ __forceinline__ float tanh_fast(float x) {
    float r; asm("tanh.approx.f32 %0, %1;" : "=f"(r) : "f"(x)); return r;
}
// add with saturation to [0,1] — matches clip(a+b, 0, 1) for finite data
__device__ __forceinline__ float addsat(float a, float b) {
    float r; asm("add.rn.sat.f32 %0, %1, %2;" : "=f"(r) : "f"(a), "f"(b)); return r;
}
__device__ __forceinline__ float4 add4(float4 a, float4 b) {
    return make_float4(a.x + b.x, a.y + b.y, a.z + b.z, a.w + b.w);
}
// horizontal 3-tap on a vertical-sum row, with clip fused into the last add
__device__ __forceinline__ float4 hfin(float l, float4 v, float rr) {
    const float pxy = v.x + v.y;
    const float pzw = v.z + v.w;
    return make_float4(addsat(l, pxy), addsat(pxy, v.z),
                       addsat(v.y, pzw), addsat(pzw, rr));
}

__global__ void __launch_bounds__(512, 2)
fused_kernel(const float* __restrict__ pred, const float* __restrict__ gt,
             float* __restrict__ out) {
    __shared__ float hb[2][64 * SSTR];          // inter-iteration halo rows
    __shared__ float red_w[16], red_g[16];

    const int tx  = threadIdx.x;            // 0..15
    const int ty  = threadIdx.y;            // 0..31
    const int tid = ty * 16 + tx;

    const int gx0b = blockIdx.x * TILE_X - 8;  // window start (logical col 0 = +4)
    const int gy0  = blockIdx.y * TILE_Y - 5;

    const bool is_l = (tx == 0);
    const bool is_r = (tx == 15);
    const int r0  = 4 * ty;
    const int col = 4 + 4 * tx;               // halo-buffer col of patch start
    const int slot_top = (ty > 0)  ? (2 * ty - 1) : 0;    // (ty-1)'s row4
    const int slot_bot = (ty < 31) ? (2 * ty + 2) : 63;   // (ty+1)'s row1

    // ---- direct global loads: 6 rows x float4 (zero-pad OOB)
    const int gxc = gx0b + col;               // global x of patch col 0
    const bool xok = (gxc >= 0) && (gxc <= IMG - 4);
    float4 rw[6];
    #pragma unroll
    for (int j = 0; j < 6; ++j) {
        const int gy = gy0 + r0 + j;
        float4 v = make_float4(0.f, 0.f, 0.f, 0.f);
        if (xok && (unsigned)gy < (unsigned)IMG)
            v = *(const float4*)(pred + (size_t)gy * IMG + gxc);
        rw[j] = v;
    }
    float4 c1 = rw[1], c2 = rw[2], c3 = rw[3], c4 = rw[4];

    // exact edge vertical sums for k=1 (edge lanes only)
    float vl0, vl1, vl2, vl3, vr0, vr1, vr2, vr3;
    if (is_l) {
        const unsigned gxl = (unsigned)(gx0b + 3);   // logical col -1
        float e[6];
        #pragma unroll
        for (int j = 0; j < 6; ++j) {
            const int gy = gy0 + r0 + j;
            e[j] = ((unsigned)gy < (unsigned)IMG && gxl < (unsigned)IMG)
                       ? pred[(size_t)gy * IMG + gxl] : 0.0f;
        }
        const float q12 = e[1] + e[2], q34 = e[3] + e[4];
        vl0 = e[0] + q12; vl1 = q12 + e[3]; vl2 = e[2] + q34; vl3 = q34 + e[5];
    }
    if (is_r) {
        const unsigned gxr = (unsigned)(gx0b + 68);  // logical col 64
        float e[6];
        #pragma unroll
        for (int j = 0; j < 6; ++j) {
            const int gy = gy0 + r0 + j;
            e[j] = ((unsigned)gy < (unsigned)IMG && gxr < (unsigned)IMG)
                       ? pred[(size_t)gy * IMG + gxr] : 0.0f;
        }
        const float q12 = e[1] + e[2], q34 = e[3] + e[4];
        vr0 = e[0] + q12; vr1 = q12 + e[3]; vr2 = e[2] + q34; vr3 = q34 + e[5];
    }

    // ---- gt for this thread's 4x4 patch; keep gh = 0.5*g
    const bool owner = (tx >= 1) && (tx < 15) && (ty >= 1) && (ty < 31);
    float4 gh[4];
    float gt_local = 0.0f;
    #pragma unroll
    for (int i = 0; i < 4; ++i) {
        const int gy = gy0 + 1 + r0 + i;
        float4 g = make_float4(0.f, 0.f, 0.f, 0.f);
        if (xok && (unsigned)gy < (unsigned)IMG)
            g = *(const float4*)(gt + (size_t)gy * IMG + gxc);
        gt_local += (g.x + g.y) + (g.z + g.w);
        gh[i] = make_float4(0.5f * g.x, 0.5f * g.y, 0.5f * g.z, 0.5f * g.w);
    }
    if (!owner) gt_local = 0.0f;

    const float wts[NITER] = {1.0f, 4.0f, 9.0f, 16.0f, 25.0f};
    float wacc = 0.0f;

    // fn for one pixel row from clipped box d, center c, gh
    auto pixrow = [](float4 d, float4 c, float4 g, float& acc) -> float4 {
        float4 fn;
        float z, t;
        z = fmaf(10.0f, d.x, fmaf(-10.0f, c.x, -5.0f));
        t = tanh_fast(z); fn.x = fmaf(g.x, t, g.x);
        z = fmaf(10.0f, d.y, fmaf(-10.0f, c.y, -5.0f));
        t = tanh_fast(z); fn.y = fmaf(g.y, t, g.y);
        z = fmaf(10.0f, d.z, fmaf(-10.0f, c.z, -5.0f));
        t = tanh_fast(z); fn.z = fmaf(g.z, t, g.z);
        z = fmaf(10.0f, d.w, fmaf(-10.0f, c.w, -5.0f));
        t = tanh_fast(z); fn.w = fmaf(g.w, t, g.w);
        acc += (fn.x + fn.y) + (fn.z + fn.w);
        return fn;
    };

    // ================= k = 1 (no barrier needed; inputs in registers) ======
    {
        const float4 s12 = add4(c1, c2);
        const float4 s34 = add4(c3, c4);
        const float4 v0 = add4(rw[0], s12);
        const float4 v1 = add4(s12, c3);
        const float4 v2 = add4(c2, s34);
        const float4 v3 = add4(s34, rw[5]);

        float l, rr;
        float fn_iter = 0.0f;

        l  = __shfl_up_sync(0xffffffffu, v0.w, 1);
        rr = __shfl_down_sync(0xffffffffu, v0.x, 1);
        if (is_l) l = vl0;
        if (is_r) rr = vr0;
        const float4 f0 = pixrow(hfin(l, v0, rr), c1, gh[0], fn_iter);

        l  = __shfl_up_sync(0xffffffffu, v1.w, 1);
        rr = __shfl_down_sync(0xffffffffu, v1.x, 1);
        if (is_l) l = vl1;
        if (is_r) rr = vr1;
        const float4 f1 = pixrow(hfin(l, v1, rr), c2, gh[1], fn_iter);

        l  = __shfl_up_sync(0xffffffffu, v2.w, 1);
        rr = __shfl_down_sync(0xffffffffu, v2.x, 1);
        if (is_l) l = vl2;
        if (is_r) rr = vr2;
        const float4 f2 = pixrow(hfin(l, v2, rr), c3, gh[2], fn_iter);

        l  = __shfl_up_sync(0xffffffffu, v3.w, 1);
        rr = __shfl_down_sync(0xffffffffu, v3.x, 1);
        if (is_l) l = vl3;
        if (is_r) rr = vr3;
        const float4 f3 = pixrow(hfin(l, v3, rr), c4, gh[3], fn_iter);

        if (owner) wacc += wts[0] * fn_iter;

        c1 = add4(c1, f0);
        c2 = add4(c2, f1);
        c3 = add4(c3, f2);
        c4 = add4(c4, f3);
        float* hdst = hb[1];
        *(float4*)&hdst[(2 * ty + 0) * SSTR + col] = c1;
        *(float4*)&hdst[(2 * ty + 1) * SSTR + col] = c4;
        __syncthreads();
    }

    // ================= k = 2..5 (no edge handling) =========================
    #pragma unroll
    for (int k = 2; k <= NITER; ++k) {
        const float* hsrc = hb[(k - 1) & 1];
        const float4 htop = *(const float4*)&hsrc[slot_top * SSTR + col];
        const float4 hbot = *(const float4*)&hsrc[slot_bot * SSTR + col];

        const float4 s12 = add4(c1, c2);
        const float4 s34 = add4(c3, c4);
        const float4 v0 = add4(htop, s12);
        const float4 v1 = add4(s12, c3);
        const float4 v2 = add4(c2, s34);
        const float4 v3 = add4(s34, hbot);

        float fn_iter = 0.0f;
        const float4 f0 = pixrow(
            hfin(__shfl_up_sync(0xffffffffu, v0.w, 1), v0,
                 __shfl_down_sync(0xffffffffu, v0.x, 1)), c1, gh[0], fn_iter);
        const float4 f1 = pixrow(
            hfin(__shfl_up_sync(0xffffffffu, v1.w, 1), v1,
                 __shfl_down_sync(0xffffffffu, v1.x, 1)), c2, gh[1], fn_iter);
        const float4 f2 = pixrow(
            hfin(__shfl_up_sync(0xffffffffu, v2.w, 1), v2,
                 __shfl_down_sync(0xffffffffu, v2.x, 1)), c3, gh[2], fn_iter);
        const float4 f3 = pixrow(
            hfin(__shfl_up_sync(0xffffffffu, v3.w, 1), v3,
                 __shfl_down_sync(0xffffffffu, v3.x, 1)), c4, gh[3], fn_iter);

        if (owner) wacc += wts[k - 1] * fn_iter;

        if (k < NITER) {
            c1 = add4(c1, f0);
            c2 = add4(c2, f1);
            c3 = add4(c3, f2);
            c4 = add4(c4, f3);
            float* hdst = hb[k & 1];
            *(float4*)&hdst[(2 * ty + 0) * SSTR + col] = c1;
            *(float4*)&hdst[(2 * ty + 1) * SSTR + col] = c4;
            __syncthreads();
        }
    }

    // ---- block reduction (16 warps), one atomic each; last block finalizes
    #pragma unroll
    for (int o = 16; o > 0; o >>= 1) {
        wacc     += __shfl_down_sync(0xffffffffu, wacc, o);
        gt_local += __shfl_down_sync(0xffffffffu, gt_local, o);
    }
    const int lane = tid & 31;
    const int wid  = tid >> 5;
    if (lane == 0) { red_w[wid] = wacc; red_g[wid] = gt_local; }
    __syncthreads();
    if (wid == 0) {
        float v = (lane < 16) ? red_w[lane] : 0.0f;
        float g = (lane < 16) ? red_g[lane] : 0.0f;
        #pragma unroll
        for (int o = 8; o > 0; o >>= 1) {
            v += __shfl_down_sync(0xffffffffu, v, o);
            g += __shfl_down_sync(0xffffffffu, g, o);
        }
        if (lane == 0) {
            atomicAdd(&g_sums[1], v);
            atomicAdd(&g_sums[0], g);
            __threadfence();
            const unsigned int done = atomicAdd(&g_count, 1u);
            if (done == NBLK - 1) {
                const float s1 = atomicAdd(&g_sums[1], 0.0f);
                const float s0 = atomicAdd(&g_sums[0], 0.0f);
                out[0] = s1 / s0;
                g_sums[0] = 0.0f;
                g_sums[1] = 0.0f;
                g_count   = 0u;
            }
        }
    }
}

extern "C" void kernel_launch(void* const* d_in, const int* in_sizes, int n_in,
                              void* d_out, int out_size) {
    (void)in_sizes; (void)n_in; (void)out_size;
    const float* pred = (const float*)d_in[0];
    const float* gt   = (const float*)d_in[1];
    float* out        = (float*)d_out;

    dim3 block(16, 32);
    dim3 grid(NTX, NTY);
    fused_kernel<<<grid, block>>>(pred, gt, out);
}

// round 15
// speedup vs baseline: 1.1038x; 1.1038x over previous
#include <cuda_runtime.h>

#define IMG 4096
#define TILE 56            // owned pixels per tile (both dims)
#define SSTR 72            // halo-row stride in floats
#define NITER 5
#define NTILES ((IMG + TILE - 1) / TILE)     // 74
#define NBLK (NTILES * NTILES)               // 5476

// [0] = gt_sum, [1] = weighted fn sum  (reset by the last block each run)
__device__ float g_sums[2];
__device__ unsigned int g_count;

// split barrier: each of 256 threads arrives twice (arrive + sync) -> 512
#define BAR_ARRIVE() asm volatile("bar.arrive 1, 512;" ::: "memory")
#define BAR_WAIT()   asm volatile("bar.sync 1, 512;"   ::: "memory")

__device__ __forceinline__ float tanh_fast(float x) {
    float r; asm("tanh.approx.f32 %0, %1;" : "=f"(r) : "f"(x)); return r;
}
// add with saturation to [0,1] — matches clip(a+b, 0, 1) for finite data
__device__ __forceinline__ float addsat(float a, float b) {
    float r; asm("add.rn.sat.f32 %0, %1, %2;" : "=f"(r) : "f"(a), "f"(b)); return r;
}
__device__ __forceinline__ float4 add4(float4 a, float4 b) {
    return make_float4(a.x + b.x, a.y + b.y, a.z + b.z, a.w + b.w);
}
// horizontal 3-tap on a vertical-sum row, with clip fused into the last add
__device__ __forceinline__ float4 hfin(float l, float4 v, float rr) {
    const float pxy = v.x + v.y;
    const float pzw = v.z + v.w;
    return make_float4(addsat(l, pxy), addsat(pxy, v.z),
                       addsat(v.y, pzw), addsat(pzw, rr));
}

__global__ void __launch_bounds__(256, 4)
fused_kernel(const float* __restrict__ pred, const float* __restrict__ gt,
             float* __restrict__ out) {
    __shared__ float hb[2][32 * SSTR];          // inter-iteration halo rows
    __shared__ float red_w[8], red_g[8];

    const int tx  = threadIdx.x;            // 0..15
    const int ty  = threadIdx.y;            // 0..15
    const int tid = ty * 16 + tx;

    const int gx0b = blockIdx.x * TILE - 8;  // window start (logical col 0 = +4)
    const int gy0  = blockIdx.y * TILE - 5;

    const bool is_l = (tx == 0);
    const bool is_r = (tx == 15);
    const int r0  = 4 * ty;
    const int col = 4 + 4 * tx;               // halo-buffer col of patch start
    const int slot_top = (ty > 0)  ? (2 * ty - 1) : 0;    // (ty-1)'s row4
    const int slot_bot = (ty < 15) ? (2 * ty + 2) : 31;   // (ty+1)'s row1

    // ---- direct global loads: 6 rows x float4 (zero-pad OOB)
    const int gxc = gx0b + col;               // global x of patch col 0
    const bool xok = (gxc >= 0) && (gxc <= IMG - 4);
    float4 rw[6];
    #pragma unroll
    for (int j = 0; j < 6; ++j) {
        const int gy = gy0 + r0 + j;
        float4 v = make_float4(0.f, 0.f, 0.f, 0.f);
        if (xok && (unsigned)gy < (unsigned)IMG)
            v = *(const float4*)(pred + (size_t)gy * IMG + gxc);
        rw[j] = v;
    }
    float4 c1 = rw[1], c2 = rw[2], c3 = rw[3], c4 = rw[4];

    // exact edge vertical sums for k=1 (edge lanes only)
    float vl0, vl1, vl2, vl3, vr0, vr1, vr2, vr3;
    if (is_l) {
        const unsigned gxl = (unsigned)(gx0b + 3);   // logical col -1
        float e[6];
        #pragma unroll
        for (int j = 0; j < 6; ++j) {
            const int gy = gy0 + r0 + j;
            e[j] = ((unsigned)gy < (unsigned)IMG && gxl < (unsigned)IMG)
                       ? pred[(size_t)gy * IMG + gxl] : 0.0f;
        }
        const float q12 = e[1] + e[2], q34 = e[3] + e[4];
        vl0 = e[0] + q12; vl1 = q12 + e[3]; vl2 = e[2] + q34; vl3 = q34 + e[5];
    }
    if (is_r) {
        const unsigned gxr = (unsigned)(gx0b + 68);  // logical col 64
        float e[6];
        #pragma unroll
        for (int j = 0; j < 6; ++j) {
            const int gy = gy0 + r0 + j;
            e[j] = ((unsigned)gy < (unsigned)IMG && gxr < (unsigned)IMG)
                       ? pred[(size_t)gy * IMG + gxr] : 0.0f;
        }
        const float q12 = e[1] + e[2], q34 = e[3] + e[4];
        vr0 = e[0] + q12; vr1 = q12 + e[3]; vr2 = e[2] + q34; vr3 = q34 + e[5];
    }

    // ---- gt for this thread's 4x4 patch; keep gh = 0.5*g
    const bool owner = (tx >= 1) && (tx < 15) && (ty >= 1) && (ty < 15);
    float4 gh[4];
    float gt_local = 0.0f;
    #pragma unroll
    for (int i = 0; i < 4; ++i) {
        const int gy = gy0 + 1 + r0 + i;
        float4 g = make_float4(0.f, 0.f, 0.f, 0.f);
        if (xok && (unsigned)gy < (unsigned)IMG)
            g = *(const float4*)(gt + (size_t)gy * IMG + gxc);
        gt_local += (g.x + g.y) + (g.z + g.w);
        gh[i] = make_float4(0.5f * g.x, 0.5f * g.y, 0.5f * g.z, 0.5f * g.w);
    }
    if (!owner) gt_local = 0.0f;

    const float wts[NITER] = {1.0f, 4.0f, 9.0f, 16.0f, 25.0f};
    float wacc = 0.0f;

    // fn for one pixel row from clipped box d, center c, gh
    auto pixrow = [](float4 d, float4 c, float4 g, float& acc) -> float4 {
        float4 fn;
        float z, t;
        z = fmaf(10.0f, d.x, fmaf(-10.0f, c.x, -5.0f));
        t = tanh_fast(z); fn.x = fmaf(g.x, t, g.x);
        z = fmaf(10.0f, d.y, fmaf(-10.0f, c.y, -5.0f));
        t = tanh_fast(z); fn.y = fmaf(g.y, t, g.y);
        z = fmaf(10.0f, d.z, fmaf(-10.0f, c.z, -5.0f));
        t = tanh_fast(z); fn.z = fmaf(g.z, t, g.z);
        z = fmaf(10.0f, d.w, fmaf(-10.0f, c.w, -5.0f));
        t = tanh_fast(z); fn.w = fmaf(g.w, t, g.w);
        acc += (fn.x + fn.y) + (fn.z + fn.w);
        return fn;
    };

    // ================= k = 1 (inputs in registers; split barrier) ==========
    {
        float fn_iter = 0.0f;
        const float4 s12 = add4(c1, c2);
        const float4 s34 = add4(c3, c4);

        // --- first half: rows 1 and 4 (produce halo values), store, arrive
        const float4 v0 = add4(rw[0], s12);
        const float4 v3 = add4(s34, rw[5]);

        float l, rr;
        l  = __shfl_up_sync(0xffffffffu, v0.w, 1);
        rr = __shfl_down_sync(0xffffffffu, v0.x, 1);
        if (is_l) l = vl0;
        if (is_r) rr = vr0;
        const float4 f0 = pixrow(hfin(l, v0, rr), c1, gh[0], fn_iter);

        l  = __shfl_up_sync(0xffffffffu, v3.w, 1);
        rr = __shfl_down_sync(0xffffffffu, v3.x, 1);
        if (is_l) l = vl3;
        if (is_r) rr = vr3;
        const float4 f3 = pixrow(hfin(l, v3, rr), c4, gh[3], fn_iter);

        c1 = add4(c1, f0);
        c4 = add4(c4, f3);
        float* hdst = hb[1];
        *(float4*)&hdst[(2 * ty + 0) * SSTR + col] = c1;
        *(float4*)&hdst[(2 * ty + 1) * SSTR + col] = c4;
        BAR_ARRIVE();

        // --- second half: rows 2 and 3 (uses OLD c2, c3)
        const float4 v1 = add4(s12, c3);
        const float4 v2 = add4(c2, s34);

        l  = __shfl_up_sync(0xffffffffu, v1.w, 1);
        rr = __shfl_down_sync(0xffffffffu, v1.x, 1);
        if (is_l) l = vl1;
        if (is_r) rr = vr1;
        const float4 f1 = pixrow(hfin(l, v1, rr), c2, gh[1], fn_iter);

        l  = __shfl_up_sync(0xffffffffu, v2.w, 1);
        rr = __shfl_down_sync(0xffffffffu, v2.x, 1);
        if (is_l) l = vl2;
        if (is_r) rr = vr2;
        const float4 f2 = pixrow(hfin(l, v2, rr), c3, gh[2], fn_iter);

        c2 = add4(c2, f1);
        c3 = add4(c3, f2);
        if (owner) wacc += wts[0] * fn_iter;
    }

    // ================= k = 2..4 (split barrier each) =======================
    #pragma unroll
    for (int k = 2; k <= NITER - 1; ++k) {
        BAR_WAIT();                              // prev stores now visible
        const float* hsrc = hb[(k - 1) & 1];
        const float4 htop = *(const float4*)&hsrc[slot_top * SSTR + col];
        const float4 hbot = *(const float4*)&hsrc[slot_bot * SSTR + col];

        float fn_iter = 0.0f;
        const float4 s12 = add4(c1, c2);
        const float4 s34 = add4(c3, c4);

        // first half: rows 1 and 4, store, arrive
        const float4 v0 = add4(htop, s12);
        const float4 v3 = add4(s34, hbot);
        const float4 f0 = pixrow(
            hfin(__shfl_up_sync(0xffffffffu, v0.w, 1), v0,
                 __shfl_down_sync(0xffffffffu, v0.x, 1)), c1, gh[0], fn_iter);
        const float4 f3 = pixrow(
            hfin(__shfl_up_sync(0xffffffffu, v3.w, 1), v3,
                 __shfl_down_sync(0xffffffffu, v3.x, 1)), c4, gh[3], fn_iter);
        c1 = add4(c1, f0);
        c4 = add4(c4, f3);
        float* hdst = hb[k & 1];
        *(float4*)&hdst[(2 * ty + 0) * SSTR + col] = c1;
        *(float4*)&hdst[(2 * ty + 1) * SSTR + col] = c4;
        BAR_ARRIVE();

        // second half: rows 2 and 3 (old c2, c3)
        const float4 v1 = add4(s12, c3);
        const float4 v2 = add4(c2, s34);
        const float4 f1 = pixrow(
            hfin(__shfl_up_sync(0xffffffffu, v1.w, 1), v1,
                 __shfl_down_sync(0xffffffffu, v1.x, 1)), c2, gh[1], fn_iter);
        const float4 f2 = pixrow(
            hfin(__shfl_up_sync(0xffffffffu, v2.w, 1), v2,
                 __shfl_down_sync(0xffffffffu, v2.x, 1)), c3, gh[2], fn_iter);
        c2 = add4(c2, f1);
        c3 = add4(c3, f2);
        if (owner) wacc += wts[k - 1] * fn_iter;
    }

    // ================= k = 5 (no stores, no further barrier) ===============
    {
        BAR_WAIT();
        const float* hsrc = hb[(NITER - 1) & 1];
        const float4 htop = *(const float4*)&hsrc[slot_top * SSTR + col];
        const float4 hbot = *(const float4*)&hsrc[slot_bot * SSTR + col];

        const float4 s12 = add4(c1, c2);
        const float4 s34 = add4(c3, c4);
        const float4 v0 = add4(htop, s12);
        const float4 v1 = add4(s12, c3);
        const float4 v2 = add4(c2, s34);
        const float4 v3 = add4(s34, hbot);

        float fn_iter = 0.0f;
        pixrow(hfin(__shfl_up_sync(0xffffffffu, v0.w, 1), v0,
                    __shfl_down_sync(0xffffffffu, v0.x, 1)), c1, gh[0], fn_iter);
        pixrow(hfin(__shfl_up_sync(0xffffffffu, v1.w, 1), v1,
                    __shfl_down_sync(0xffffffffu, v1.x, 1)), c2, gh[1], fn_iter);
        pixrow(hfin(__shfl_up_sync(0xffffffffu, v2.w, 1), v2,
                    __shfl_down_sync(0xffffffffu, v2.x, 1)), c3, gh[2], fn_iter);
        pixrow(hfin(__shfl_up_sync(0xffffffffu, v3.w, 1), v3,
                    __shfl_down_sync(0xffffffffu, v3.x, 1)), c4, gh[3], fn_iter);
        if (owner) wacc += wts[NITER - 1] * fn_iter;
    }

    // ---- block reduction, one atomic each per block; last block finalizes
    #pragma unroll
    for (int o = 16; o > 0; o >>= 1) {
        wacc     += __shfl_down_sync(0xffffffffu, wacc, o);
        gt_local += __shfl_down_sync(0xffffffffu, gt_local, o);
    }
    const int lane = tid & 31;
    const int wid  = tid >> 5;
    if (lane == 0) { red_w[wid] = wacc; red_g[wid] = gt_local; }
    __syncthreads();
    if (tid == 0) {
        float v = 0.0f, g = 0.0f;
        #pragma unroll
        for (int i = 0; i < 8; ++i) { v += red_w[i]; g += red_g[i]; }
        atomicAdd(&g_sums[1], v);
        atomicAdd(&g_sums[0], g);
        __threadfence();
        const unsigned int done = atomicAdd(&g_count, 1u);
        if (done == NBLK - 1) {
            const float s1 = atomicAdd(&g_sums[1], 0.0f);
            const float s0 = atomicAdd(&g_sums[0], 0.0f);
            out[0] = s1 / s0;
            g_sums[0] = 0.0f;
            g_sums[1] = 0.0f;
            g_count   = 0u;
        }
    }
}

extern "C" void kernel_launch(void* const* d_in, const int* in_sizes, int n_in,
                              void* d_out, int out_size) {
    (void)in_sizes; (void)n_in; (void)out_size;
    const float* pred = (const float*)d_in[0];
    const float* gt   = (const float*)d_in[1];
    float* out        = (float*)d_out;

    dim3 block(16, 16);
    dim3 grid(NTILES, NTILES);
    fused_kernel<<<grid, block>>>(pred, gt, out);
}